// round 1
// baseline (speedup 1.0000x reference)
#include <cuda_runtime.h>

// Problem: out[o*256+k][h][m] = sum_{i,j} w[i][k][j] * t[o,i,(h-1)%14, m+j-1]
//          t[o,i,n,m'] = x[o*256+i][n][(m'-1)%14],  m+j-1 zero-padded to [0,13]
//
// Decomposition: grid (ich=4, o*kt=4, h=14) = 224 blocks x 128 threads.
// Each block: one i-chunk of 64, one (o, k-tile of 128), one output row h.
// Thread = one output channel k, 14 accumulators over m.
// Partials -> __device__ scratch, reduced by a second kernel.

#define ICH   4
#define ILEN  64
#define KB    128

__device__ float g_partial[ICH * 512 * 196];

__global__ __launch_bounds__(128) void conv_kernel(const float* __restrict__ x,
                                                   const float* __restrict__ w) {
    const int ich = blockIdx.x;          // 0..3   (i chunk)
    const int okt = blockIdx.y;          // 0..3   (o = okt>>1, kt = okt&1)
    const int h   = blockIdx.z;          // 0..13  (output row, post H-roll)
    const int o   = okt >> 1;
    const int kt  = okt & 1;
    const int tx  = threadIdx.x;         // 0..127
    const int k   = kt * KB + tx;        // output channel within group
    const int n   = (h + 13) % 14;       // source H row (undo roll along H)

    // sx[il][mm]: zero-padded, W-rolled input row.
    // mm in [1,14] -> t[o, i, n, mm-1] = x[o*256+i][n][(mm-2) mod 14]; mm=0,15 -> 0
    __shared__ float sx[ILEN][16];
    for (int idx = tx; idx < ILEN * 16; idx += 128) {
        const int il = idx >> 4;
        const int mm = idx & 15;
        float v = 0.f;
        if (mm >= 1 && mm <= 14) {
            const int wi = (mm + 12) % 14;
            const int i  = ich * ILEN + il;
            v = x[((o * 256 + i) * 14 + n) * 14 + wi];
        }
        sx[il][mm] = v;
    }
    __syncthreads();

    float acc[14];
#pragma unroll
    for (int m = 0; m < 14; m++) acc[m] = 0.f;

    // w[i][k][j] at element offset (i*256 + k)*3
    const float* wbase = w + ((size_t)(ich * ILEN) * 256 + k) * 3;

#pragma unroll 4
    for (int il = 0; il < ILEN; ++il) {
        const float* wp = wbase + (size_t)il * (256 * 3);
        const float w0 = wp[0];
        const float w1 = wp[1];
        const float w2 = wp[2];

        const float4 x0 = *(const float4*)&sx[il][0];
        const float4 x1 = *(const float4*)&sx[il][4];
        const float4 x2 = *(const float4*)&sx[il][8];
        const float4 x3 = *(const float4*)&sx[il][12];
        float xr[16];
        xr[0]=x0.x; xr[1]=x0.y; xr[2]=x0.z; xr[3]=x0.w;
        xr[4]=x1.x; xr[5]=x1.y; xr[6]=x1.z; xr[7]=x1.w;
        xr[8]=x2.x; xr[9]=x2.y; xr[10]=x2.z; xr[11]=x2.w;
        xr[12]=x3.x; xr[13]=x3.y; xr[14]=x3.z; xr[15]=x3.w;

#pragma unroll
        for (int m = 0; m < 14; m++) {
            acc[m] += w0 * xr[m];
            acc[m] += w1 * xr[m + 1];
            acc[m] += w2 * xr[m + 2];
        }
    }

    // partial layout: [ich][c=o*256+k][196]; per-thread 14 contiguous floats
    float* pp = g_partial + ((size_t)(ich * 512 + o * 256 + k) * 196 + h * 14);
#pragma unroll
    for (int m = 0; m < 14; m += 2) {
        float2 v; v.x = acc[m]; v.y = acc[m + 1];
        *(float2*)&pp[m] = v;   // 8B-aligned: base offset is multiple of 56B? h*14*4 = 56B*h, 8B-aligned; row base 784B*c is 16B-aligned
    }
}

__global__ __launch_bounds__(256) void reduce_kernel(float* __restrict__ out) {
    const int t = blockIdx.x * 256 + threadIdx.x;
    if (t < 512 * 196) {
        float s = g_partial[t]
                + g_partial[1 * 512 * 196 + t]
                + g_partial[2 * 512 * 196 + t]
                + g_partial[3 * 512 * 196 + t];
        out[t] = s;
    }
}

extern "C" void kernel_launch(void* const* d_in, const int* in_sizes, int n_in,
                              void* d_out, int out_size) {
    const float* x = (const float*)d_in[0];   // (1,512,14,14) = 100352 floats
    const float* w = (const float*)d_in[1];   // (256,256,3)   = 196608 floats
    float* out = (float*)d_out;               // (1,512,14,14)

    dim3 grid(ICH, 4, 14);
    conv_kernel<<<grid, 128>>>(x, w);
    reduce_kernel<<<(512 * 196 + 255) / 256, 256>>>(out);
}